// round 4
// baseline (speedup 1.0000x reference)
#include <cuda_runtime.h>
#include <math_constants.h>

// x [B=32, C=256, H=64, W=64] fp32
#define B    32
#define C    256
#define HW   4096
#define W64  64

#define NBB    16              // batch size in b  (x-slice = 67 MB < 126 MB L2)
#define NBATCH (B / NBB)       // 2

// ---- reduce tiling ----
#define K1T    128
#define HWT    512
#define NHWT   (HW / HWT)      // 8
#define CR     32
#define NCR    (C / CR)        // 8
#define CHUNK  4
#define NCH    (CR / CHUNK)    // 8
#define RED_PER_B  (NCR * NHWT)        // 64 reduce CTAs per b
#define RED_CTAS   (NBB * RED_PER_B)   // 1024
#define WGT_CTAS   (NBB * 5)           // 80 (1 chw + 4 spatial tiles per b)

// ---- scratch (device globals; allocation-free) ----
__device__ float    g_cpart[B * NHWT * C];
__device__ float4   g_pmax[NCR][B * HW / 4];
__device__ float4   g_psum[NCR][B * HW / 4];
__device__ float    g_chw[B * C];
__device__ float4   g_sp4[B * HW / 4];
__device__ unsigned g_cnt[B];          // per-b reduce-CTA arrival counter

// smem pool shared by all roles: max is spatial (2*22*72 + 99 floats)
#define POOL_FLOATS (2 * 22 * 72 + 100)

// =====================================================================
// kR: reduce CTAs (bid < RED_CTAS) stream x and emit partials; then
//     weight CTAs (80, highest bids) spin on per-b counters and compute
//     the channel weight (conv1d+sigmoid) and spatial weight (7x7 conv).
//     Deadlock-free: reduce CTAs never wait; weight CTAs are 7% of grid.
// =====================================================================
__global__ __launch_bounds__(K1T, 8) void kR(const float* __restrict__ x,
                                             const float* __restrict__ w1d,
                                             const float* __restrict__ w2d,
                                             const float* __restrict__ bias,
                                             int b0)
{
    __shared__ float pool[POOL_FLOATS];
    const int bid  = blockIdx.x;
    const int tid  = threadIdx.x;
    const int warp = tid >> 5;
    const int lane = tid & 31;

    if (bid < RED_CTAS) {
        // ---------------- reduce role ----------------
        const int b  = b0 + (bid >> 6);
        const int cr = (bid >> 3) & 7;
        const int ht = bid & 7;

        float (*sbuf)[CHUNK][K1T] = (float (*)[CHUNK][K1T])pool;

        const float4* __restrict__ xp =
            (const float4*)x + ((long)(b * C + cr * CR) * HW + ht * HWT) / 4 + tid;

        float4 mx = make_float4(-CUDART_INF_F, -CUDART_INF_F, -CUDART_INF_F, -CUDART_INF_F);
        float4 sm = make_float4(0.f, 0.f, 0.f, 0.f);

        float4 p[CHUNK];
        #pragma unroll
        for (int j = 0; j < CHUNK; ++j) p[j] = xp[j * (HW / 4)];

        #pragma unroll 2
        for (int ch = 0; ch < NCH; ++ch) {
            float4 v[CHUNK];
            #pragma unroll
            for (int j = 0; j < CHUNK; ++j) v[j] = p[j];

            float (*sb)[K1T] = sbuf[ch & 1];
            #pragma unroll
            for (int j = 0; j < CHUNK; ++j)
                sb[j][tid] = (v[j].x + v[j].y) + (v[j].z + v[j].w);

            if (ch + 1 < NCH) {
                #pragma unroll
                for (int j = 0; j < CHUNK; ++j)
                    p[j] = xp[((ch + 1) * CHUNK + j) * (HW / 4)];
            }

            #pragma unroll
            for (int j = 0; j < CHUNK; ++j) {
                mx.x = fmaxf(mx.x, v[j].x); mx.y = fmaxf(mx.y, v[j].y);
                mx.z = fmaxf(mx.z, v[j].z); mx.w = fmaxf(mx.w, v[j].w);
                sm.x += v[j].x; sm.y += v[j].y; sm.z += v[j].z; sm.w += v[j].w;
            }

            __syncthreads();
            float r = (sb[warp][lane]      + sb[warp][lane + 32])
                    + (sb[warp][lane + 64] + sb[warp][lane + 96]);
            r += __shfl_xor_sync(0xffffffffu, r, 16);
            r += __shfl_xor_sync(0xffffffffu, r, 8);
            r += __shfl_xor_sync(0xffffffffu, r, 4);
            r += __shfl_xor_sync(0xffffffffu, r, 2);
            r += __shfl_xor_sync(0xffffffffu, r, 1);
            if (lane == 0)
                g_cpart[(b * NHWT + ht) * C + cr * CR + ch * CHUNK + warp] = r;
        }

        const int o = b * (HW / 4) + ht * (HWT / 4) + tid;
        g_pmax[cr][o] = mx;
        g_psum[cr][o] = sm;

        __threadfence();
        __syncthreads();
        if (tid == 0) atomicAdd(&g_cnt[b], 1u);
    } else {
        // ---------------- weight role ----------------
        const int w    = bid - RED_CTAS;
        const int b    = b0 + w / 5;
        const int role = w % 5;

        if (tid == 0) {
            while (*(volatile unsigned*)&g_cnt[b] < RED_PER_B) __nanosleep(200);
        }
        __syncthreads();

        if (role == 0) {
            // channel weight: mean -> conv1d(5, pad 2) -> sigmoid
            float* mean = pool;
            #pragma unroll
            for (int c = tid; c < C; c += K1T) {
                float acc = 0.f;
                #pragma unroll
                for (int ht = 0; ht < NHWT; ++ht)
                    acc += g_cpart[(b * NHWT + ht) * C + c];
                mean[c] = acc * (1.0f / (float)HW);
            }
            __syncthreads();
            #pragma unroll
            for (int c = tid; c < C; c += K1T) {
                float y = 0.f;
                #pragma unroll
                for (int k = 0; k < 5; ++k) {
                    int cc = c - 2 + k;
                    float m = (cc >= 0 && cc < C) ? mean[cc] : 0.f;
                    y += w1d[k] * m;
                }
                g_chw[b * C + c] = 1.0f / (1.0f + expf(-y));
            }
        } else {
            // spatial weight tile: rows [r0, r0+16)
            const int r0 = (role - 1) * 16;
            float* smax = pool;
            float* savg = pool + 22 * 72;
            float* sw   = pool + 2 * 22 * 72;   // 98 taps + bias at [98]

            for (int i = tid; i < 22 * 70; i += K1T) {
                int rr = i / 70, cc = i % 70;
                int gr = r0 - 3 + rr, gc = cc - 3;
                float mv = 0.f, av = 0.f;
                if (gr >= 0 && gr < W64 && gc >= 0 && gc < W64) {
                    int gi = b * HW + gr * W64 + gc;
                    mv = -CUDART_INF_F;
                    #pragma unroll
                    for (int r = 0; r < NCR; ++r) {
                        mv = fmaxf(mv, ((const float*)g_pmax[r])[gi]);
                        av += ((const float*)g_psum[r])[gi];
                    }
                    av *= (1.0f / (float)C);
                }
                smax[rr * 72 + cc] = mv;
                savg[rr * 72 + cc] = av;
            }
            if (tid < 98) sw[tid] = w2d[tid];
            if (tid == 0) sw[98] = bias[0];
            __syncthreads();

            float* __restrict__ sp = (float*)g_sp4;
            #pragma unroll
            for (int k = 0; k < 8; ++k) {
                int oi   = tid + k * K1T;      // 0..1023
                int orow = oi >> 6;
                int ocol = oi & 63;
                float acc = sw[98];
                #pragma unroll
                for (int kh = 0; kh < 7; ++kh) {
                    #pragma unroll
                    for (int kw = 0; kw < 7; ++kw) {
                        acc += sw[kh * 7 + kw]      * smax[(orow + kh) * 72 + ocol + kw];
                        acc += sw[49 + kh * 7 + kw] * savg[(orow + kh) * 72 + ocol + kw];
                    }
                }
                sp[b * HW + (r0 + orow) * W64 + ocol] = 1.0f / (1.0f + expf(-acc));
            }
        }
    }
}

// =====================================================================
// kA: out = x * (chw[b,c] + sp[b,hw] + 1) for one batch.
//     x-read hits L2 (just streamed by kR); __ldcs demotes it so the
//     next batch has room. Also resets this batch's counters for the
//     next graph replay.
// =====================================================================
__global__ __launch_bounds__(256) void kA(const float4* __restrict__ x4,
                                          float4* __restrict__ out4,
                                          int b0)
{
    if (blockIdx.x == 0 && threadIdx.x < NBB) g_cnt[b0 + threadIdx.x] = 0;

    const int i4  = b0 * (C * HW / 4) + blockIdx.x * 256 + threadIdx.x;
    const int hw4 = i4 & 1023;
    const int bc  = i4 >> 10;
    const int b   = bc >> 8;

    const float  cw = g_chw[bc] + 1.0f;
    const float4 sp = g_sp4[b * 1024 + hw4];
    const float4 v  = __ldcs(&x4[i4]);

    float4 o;
    o.x = v.x * (cw + sp.x);
    o.y = v.y * (cw + sp.y);
    o.z = v.z * (cw + sp.z);
    o.w = v.w * (cw + sp.w);
    __stcs(&out4[i4], o);
}

// =====================================================================
extern "C" void kernel_launch(void* const* d_in, const int* in_sizes, int n_in,
                              void* d_out, int out_size)
{
    const float* x    = (const float*)d_in[0];  // [32,256,64,64]
    const float* w1d  = (const float*)d_in[1];  // [1,1,5]
    const float* w2d  = (const float*)d_in[2];  // [1,2,7,7]
    const float* bias = (const float*)d_in[3];  // [1]
    float* out = (float*)d_out;

    for (int bb = 0; bb < NBATCH; ++bb) {
        kR<<<RED_CTAS + WGT_CTAS, K1T>>>(x, w1d, w2d, bias, bb * NBB);
        kA<<<NBB * C * (HW / 4) / 256, 256>>>((const float4*)x, (float4*)out, bb * NBB);
    }
}